// round 7
// baseline (speedup 1.0000x reference)
#include <cuda_runtime.h>
#include <math.h>
#include <stdint.h>

#define CONTF 13
#define CATEF 26
#define NF    39
#define ED    40
#define NA    8
#define TPB   480
#define NW    15      // warps per block = tiles of the 5x5 upper-tri tiling
#define PAD   44      // 176B row stride: 16B-aligned, conflict-free LDS.128
#define XROWS 40      // 39 real rows + 1 zero pad row (row 39)
#define XSZ   (XROWS*PAD)
#define VOCAB 100000
#define NBLK  296     // 2 persistent blocks per SM

typedef unsigned long long u64;

__device__ __forceinline__ u64 mul2(u64 a, u64 b) {
    u64 d; asm("mul.rn.f32x2 %0, %1, %2;" : "=l"(d) : "l"(a), "l"(b)); return d;
}
__device__ __forceinline__ u64 fma2(u64 a, u64 b, u64 c) {
    u64 d; asm("fma.rn.f32x2 %0, %1, %2, %3;" : "=l"(d) : "l"(a), "l"(b), "l"(c)); return d;
}
__device__ __forceinline__ u64 pk2(float lo, float hi) {
    u64 d; asm("mov.b64 %0, {%1, %2};" : "=l"(d) : "f"(lo), "f"(hi)); return d;
}
__device__ __forceinline__ void unpack2(u64 v, float& lo, float& hi) {
    asm("mov.b64 {%0, %1}, %2;" : "=f"(lo), "=f"(hi) : "l"(v));
}
__device__ __forceinline__ float sum2(u64 v) {
    float lo, hi; unpack2(v, lo, hi); return lo + hi;
}
__device__ __forceinline__ void cp16(uint32_t dst, const void* src) {
    asm volatile("cp.async.ca.shared.global [%0], [%1], 16;" :: "r"(dst), "l"(src));
}
__device__ __forceinline__ void cp4(uint32_t dst, const void* src) {
    asm volatile("cp.async.ca.shared.global [%0], [%1], 4;" :: "r"(dst), "l"(src));
}

__global__ __launch_bounds__(TPB, 2) void afm_main(
    const float* __restrict__ conts,
    const void*  __restrict__ cates_raw,
    const float* __restrict__ emb,
    const float* __restrict__ attn_W,   // (8, 40)
    const float* __restrict__ attn_b,   // (8,)
    const float* __restrict__ proj_W,   // (1, 8)
    const float* __restrict__ fc_W,     // (1, 40)
    const float* __restrict__ fc_b,     // (1,)
    float* __restrict__ out,            // (B, 1)
    int batch)
{
    __shared__ __align__(16) float xs[2][XSZ];       // double-buffered x tiles
    __shared__ __align__(16) ulonglong2 Wq[ED * 2];  // per d: (W0d,W1d),(W2d,W3d)|(W4d,W5d),(W6d,W7d)
    __shared__ __align__(16) ulonglong2 fp2[10];     // fc_W packed, 4 dims/entry
    __shared__ float sbase[CONTF * ED];              // emb rows 0..12
    __shared__ float sconts[2][CONTF];
    __shared__ float pwb[2 * NA];                    // attn_b | proj_W
    __shared__ float sredm[NW], sreds[NW], sredq[NW];
    __shared__ int   sflag;

    const int t    = threadIdx.x;
    const int lane = t & 31;
    const int wid  = t >> 5;

    // --- int64-vs-int32 probe: int64 indices < VOCAB -> all hi words 0 ---
    if (wid == 0) {
        const unsigned int* raw = (const unsigned int*)cates_raw;
        unsigned int lo = raw[2 * lane], hi = raw[2 * lane + 1];
        int ok = (hi == 0u && lo < (unsigned)VOCAB);
        unsigned int bal = __ballot_sync(0xffffffffu, ok);
        if (lane == 0) sflag = (bal == 0xffffffffu);
    }

    // --- block-lifetime parameter setup ---
    // Wq entries: ((u64*)Wq)[d*4 + k] = (W[2k][d], W[2k+1][d])
    for (int e = t; e < ED * 4; e += TPB) {
        int d = e >> 2, k = e & 3;
        ((u64*)Wq)[e] = pk2(attn_W[(2 * k) * ED + d], attn_W[(2 * k + 1) * ED + d]);
    }
    if (t < 10) {
        ulonglong2 v;
        v.x = pk2(fc_W[4 * t], fc_W[4 * t + 1]);
        v.y = pk2(fc_W[4 * t + 2], fc_W[4 * t + 3]);
        fp2[t] = v;
    }
    if (t < NA) { pwb[t] = attn_b[t]; pwb[NA + t] = proj_W[t]; }
    for (int e = t; e < CONTF * ED; e += TPB) sbase[e] = emb[e];
    // zero pad row 39 of both buffers (never written by prefetch)
    if (t < 2 * PAD) {
        int buf = t / PAD, d = t - buf * PAD;
        xs[buf][39 * PAD + d] = 0.f;
    }
    __syncthreads();

    const int is64 = sflag;
    const long long* c64 = (const long long*)cates_raw;
    const int*       c32 = (const int*)cates_raw;
    const float fcb = fc_b[0];

    const uint32_t xs_a = (uint32_t)__cvta_generic_to_shared(&xs[0][0]);
    const uint32_t sc_a = (uint32_t)__cvta_generic_to_shared(&sconts[0][0]);

    // --- warp -> 8x8 tile (bi, bj), bi <= bj, of the 5x5 block grid ---
    int bi = 0, rem = wid;
    while (rem >= 5 - bi) { rem -= 5 - bi; bi++; }
    const int bj = bi + rem;
    const int ii0 = lane >> 3, jj = lane & 7;
    const int i0 = bi * 8 + ii0;       // slot0 row
    const int i1 = i0 + 4;             // slot1 row
    const int j  = bj * 8 + jj;        // shared column row
    const bool valid0 = (i0 < j) && (j < NF);
    const bool valid1 = (i1 < j) && (j < NF);
    const int or0 = i0 * PAD, or1 = i1 * PAD, oc = j * PAD;

    // --- prefetch: 26 gathered rows (260 threads x 16B) + 13 conts ---
    #define PREFETCH(b_, buf_) do {                                           \
        if (t < 260) {                                                        \
            int f_ = t / 10, seg_ = t - f_ * 10;                              \
            long long idx_ = is64 ? c64[(long long)(b_) * CATEF + f_]         \
                                  : (long long)c32[(b_) * CATEF + f_];        \
            cp16(xs_a + ((buf_) * XSZ + (CONTF + f_) * PAD + seg_ * 4) * 4,   \
                 emb + idx_ * ED + seg_ * 4);                                 \
        } else if (t < 260 + CONTF) {                                         \
            int r_ = t - 260;                                                 \
            cp4(sc_a + ((buf_) * CONTF + r_) * 4, conts + (b_) * CONTF + r_); \
        }                                                                     \
        asm volatile("cp.async.commit_group;" ::: "memory");                  \
    } while (0)

    const int s0 = blockIdx.x;
    int parity = 0;
    if (s0 < batch) PREFETCH(s0, 0);

    for (int s = s0; s < batch; s += NBLK) {
        float* xb = &xs[parity][0];

        asm volatile("cp.async.wait_group 0;" ::: "memory");
        __syncthreads();

        if (s + NBLK < batch) PREFETCH(s + NBLK, parity ^ 1);

        // build continuous-field rows: sbase * conts[s]
        for (int e = t; e < CONTF * ED; e += TPB) {
            int r = e / ED, d = e - r * ED;
            xb[r * PAD + d] = sbase[e] * sconts[parity][r];
        }
        __syncthreads();

        // a-packed accumulators: acc[k] = (h[2k], h[2k+1]) partial sums
        u64 acc0[4], acc1[4];
        #pragma unroll
        for (int k = 0; k < 4; k++) { acc0[k] = 0ull; acc1[k] = 0ull; }
        u64 q0 = 0ull, q1 = 0ull;

        #pragma unroll
        for (int dv = 0; dv < 10; dv++) {            // 4 dims per iter
            ulonglong2 r0 = *(const ulonglong2*)(xb + or0 + dv * 4);
            ulonglong2 r1 = *(const ulonglong2*)(xb + or1 + dv * 4);
            ulonglong2 cc = *(const ulonglong2*)(xb + oc  + dv * 4);
            u64 e0a = mul2(r0.x, cc.x), e0b = mul2(r0.y, cc.y);
            u64 e1a = mul2(r1.x, cc.x), e1b = mul2(r1.y, cc.y);

            ulonglong2 fv = fp2[dv];
            q0 = fma2(e0a, fv.x, q0); q0 = fma2(e0b, fv.y, q0);
            q1 = fma2(e1a, fv.x, q1); q1 = fma2(e1b, fv.y, q1);

            float f0[4], f1[4];
            unpack2(e0a, f0[0], f0[1]); unpack2(e0b, f0[2], f0[3]);
            unpack2(e1a, f1[0], f1[1]); unpack2(e1b, f1[2], f1[3]);

            #pragma unroll
            for (int dd = 0; dd < 4; dd++) {
                int d = dv * 4 + dd;
                ulonglong2 w01 = Wq[d * 2];
                ulonglong2 w23 = Wq[d * 2 + 1];
                u64 sd0 = pk2(f0[dd], f0[dd]);
                u64 sd1 = pk2(f1[dd], f1[dd]);
                acc0[0] = fma2(sd0, w01.x, acc0[0]);
                acc0[1] = fma2(sd0, w01.y, acc0[1]);
                acc0[2] = fma2(sd0, w23.x, acc0[2]);
                acc0[3] = fma2(sd0, w23.y, acc0[3]);
                acc1[0] = fma2(sd1, w01.x, acc1[0]);
                acc1[1] = fma2(sd1, w01.y, acc1[1]);
                acc1[2] = fma2(sd1, w23.x, acc1[2]);
                acc1[3] = fma2(sd1, w23.y, acc1[3]);
            }
        }

        // --- logits: relu + proj ---
        float g0 = 0.f, g1 = 0.f;
        #pragma unroll
        for (int k = 0; k < 4; k++) {
            float ha, hb;
            unpack2(acc0[k], ha, hb);
            g0 += pwb[NA + 2 * k]     * fmaxf(ha + pwb[2 * k], 0.f);
            g0 += pwb[NA + 2 * k + 1] * fmaxf(hb + pwb[2 * k + 1], 0.f);
            unpack2(acc1[k], ha, hb);
            g1 += pwb[NA + 2 * k]     * fmaxf(ha + pwb[2 * k], 0.f);
            g1 += pwb[NA + 2 * k + 1] * fmaxf(hb + pwb[2 * k + 1], 0.f);
        }
        float qs0 = sum2(q0), qs1 = sum2(q1);

        // --- block max over valid slots ---
        float m = fmaxf(valid0 ? g0 : -1e30f, valid1 ? g1 : -1e30f);
        #pragma unroll
        for (int o = 16; o; o >>= 1) m = fmaxf(m, __shfl_xor_sync(0xffffffffu, m, o));
        if (lane == 0) sredm[wid] = m;
        __syncthreads();
        float gmax = sredm[0];
        #pragma unroll
        for (int k = 1; k < NW; k++) gmax = fmaxf(gmax, sredm[k]);

        float w0 = valid0 ? __expf(g0 - gmax) : 0.f;
        float w1 = valid1 ? __expf(g1 - gmax) : 0.f;

        // --- block sums of (w, w*q) ---
        float ssum = w0 + w1;
        float sq   = w0 * qs0 + w1 * qs1;
        #pragma unroll
        for (int o = 16; o; o >>= 1) {
            ssum += __shfl_xor_sync(0xffffffffu, ssum, o);
            sq   += __shfl_xor_sync(0xffffffffu, sq,   o);
        }
        if (lane == 0) { sreds[wid] = ssum; sredq[wid] = sq; }
        __syncthreads();

        if (t == 0) {
            float ts = 0.f, tq = 0.f;
            #pragma unroll
            for (int k = 0; k < NW; k++) { ts += sreds[k]; tq += sredq[k]; }
            float z = tq / ts + fcb;
            out[s] = 1.f / (1.f + __expf(-z));
        }
        parity ^= 1;
    }
}

extern "C" void kernel_launch(void* const* d_in, const int* in_sizes, int n_in,
                              void* d_out, int out_size) {
    const float* conts  = (const float*)d_in[0];
    const void*  cates  = d_in[1];
    const float* emb    = (const float*)d_in[3];
    const float* attn_W = (const float*)d_in[4];
    const float* attn_b = (const float*)d_in[5];
    const float* proj_W = (const float*)d_in[6];
    const float* fc_W   = (const float*)d_in[7];
    const float* fc_b   = (const float*)d_in[8];
    float* out = (float*)d_out;

    int batch = in_sizes[0] / CONTF;
    int nblk = batch < NBLK ? batch : NBLK;
    afm_main<<<nblk, TPB>>>(conts, cates, emb, attn_W, attn_b, proj_W,
                            fc_W, fc_b, out, batch);
}